// round 14
// baseline (speedup 1.0000x reference)
#include <cuda_runtime.h>
#include <cuda_fp16.h>
#include <cstdint>

// ---- SMEM layout (bytes) ----
#define OFF_OUTA 0
#define OFF_OUTB 32768
#define OFF_WIM0 65536
#define OFF_WIM1 98304
#define OFF_W1   131072
#define OFF_W2   163840
#define OFF_C0   196608   // float2[2][128] double-buffered (wz,bi) = 2KB
#define OFF_WFD  198656   // float[2][128] double-buffered Wf = 1KB
#define OFF_B12  199680   // float2[128] (b1,b2) = 1KB
#define SMEM_TOTAL 200704

// ---- device scratch ----
__device__ __half g_WiM[(size_t)128 * 16384];  // per-i swizzled 128x128 fp16 image
__device__ float  g_wz[128 * 128];
__device__ __half g_W1h[16384];                // swizzled image
__device__ __half g_W2h[16384];
__device__ float  g_zT[(size_t)128 * 131072];  // [i][b]

// XOR-swizzled byte offset in a 128x128 fp16 tile (row = 256B)
__host__ __device__ __forceinline__ uint32_t tile_off(int r, int c) {
    return (uint32_t)(r * 256 + ((c * 2) ^ ((r & 7) << 4)));
}

// ---- prologue kernels ----
__global__ void prep_weights(const float* __restrict__ Wi, const float* __restrict__ M,
                             const float* __restrict__ W1, const float* __restrict__ W2) {
    int i = blockIdx.x;
    if (i < 128) {
        const float* Wii = Wi + (size_t)i * 16512;   // 128*129
        for (int v = threadIdx.x; v < 16384; v += blockDim.x) {
            int j = v >> 7, k = v & 127;
            float m = (k == i) ? 0.f : M[k * 128 + i];
            g_WiM[(size_t)i * 16384 + (tile_off(j, k) >> 1)] = __float2half(Wii[j * 129 + k] * m);
        }
        for (int j = threadIdx.x; j < 128; j += blockDim.x)
            g_wz[i * 128 + j] = Wii[j * 129 + 128];
    } else if (i == 128) {
        for (int v = threadIdx.x; v < 16384; v += blockDim.x)
            g_W1h[tile_off(v >> 7, v & 127) >> 1] = __float2half(W1[v]);
    } else {
        for (int v = threadIdx.x; v < 16384; v += blockDim.x)
            g_W2h[tile_off(v >> 7, v & 127) >> 1] = __float2half(W2[v]);
    }
}

__global__ void transpose_z(const float* __restrict__ z, int Bn) {
    __shared__ float t[32][33];
    int b0 = blockIdx.x * 32, i0 = blockIdx.y * 32;
    #pragma unroll
    for (int r = threadIdx.y; r < 32; r += 8)
        t[r][threadIdx.x] = z[(size_t)(b0 + r) * 128 + i0 + threadIdx.x];
    __syncthreads();
    #pragma unroll
    for (int r = threadIdx.y; r < 32; r += 8)
        g_zT[(size_t)(i0 + r) * Bn + b0 + threadIdx.x] = t[threadIdx.x][r];
}

// ---- mma helpers ----
__device__ __forceinline__ void ldsm4(uint32_t addr, uint32_t* r) {
    asm volatile("ldmatrix.sync.aligned.m8n8.x4.shared.b16 {%0,%1,%2,%3},[%4];"
        : "=r"(r[0]), "=r"(r[1]), "=r"(r[2]), "=r"(r[3]) : "r"(addr));
}
__device__ __forceinline__ void mma16816(float* c, const uint32_t* a, const uint32_t* b) {
    asm volatile("mma.sync.aligned.m16n8k16.row.col.f32.f16.f16.f32 "
        "{%0,%1,%2,%3},{%4,%5,%6,%7},{%8,%9},{%0,%1,%2,%3};"
        : "+f"(c[0]), "+f"(c[1]), "+f"(c[2]), "+f"(c[3])
        : "r"(a[0]), "r"(a[1]), "r"(a[2]), "r"(a[3]), "r"(b[0]), "r"(b[1]));
}
__device__ __forceinline__ void cpa16(uint32_t s, const void* g) {
    asm volatile("cp.async.cg.shared.global [%0],[%1],16;" :: "r"(s), "l"(g));
}

// ---- GEMM over full N=128, A from smem (G0). Warp rows: mrowT..mrowT+16*NMT ----
template<int NMT>
__device__ __forceinline__ void gemm_s(uint32_t aTile, int mrowT, uint32_t bBase,
                                       float (*acc)[16][4], int lane) {
    #pragma unroll
    for (int mt = 0; mt < NMT; mt++)
        #pragma unroll
        for (int nb = 0; nb < 16; nb++)
            #pragma unroll
            for (int c = 0; c < 4; c++) acc[mt][nb][c] = 0.f;

    const uint32_t xorA = (uint32_t)((lane & 7) << 4);
    const uint32_t cA = (lane & 16) ? 16u : 0u;
    uint32_t rowA[NMT];
    #pragma unroll
    for (int mt = 0; mt < NMT; mt++)
        rowA[mt] = aTile + (uint32_t)((mrowT + mt * 16 + (lane & 15)) * 256);
    const uint32_t rowW = bBase + (uint32_t)((((lane & 7) + ((lane & 16) ? 8 : 0))) * 256);
    const uint32_t xorB = (uint32_t)((lane & 7) << 4);
    const uint32_t cB = (lane & 8) ? 16u : 0u;

    #pragma unroll
    for (int ks = 0; ks < 8; ks++) {
        uint32_t offA = ((uint32_t)(ks * 32) + cA) ^ xorA;
        uint32_t offB = ((uint32_t)(ks * 32) + cB) ^ xorB;
        uint32_t a[NMT][4], b[32];
        #pragma unroll
        for (int mt = 0; mt < NMT; mt++) ldsm4(rowA[mt] + offA, a[mt]);
        #pragma unroll
        for (int q = 0; q < 8; q++) ldsm4(rowW + (uint32_t)(q * 4096) + offB, b + 4 * q);
        #pragma unroll
        for (int nb = 0; nb < 16; nb++)
            #pragma unroll
            for (int mt = 0; mt < NMT; mt++)
                mma16816(acc[mt][nb], a[mt], b + 2 * nb);
    }
}

// ---- GEMM over full N=128, A from registers (hf: C->A fragment identity) ----
template<int NMT>
__device__ __forceinline__ void gemm_r(const uint32_t (*hf)[32], uint32_t bBase,
                                       float (*acc)[16][4], int lane) {
    #pragma unroll
    for (int mt = 0; mt < NMT; mt++)
        #pragma unroll
        for (int nb = 0; nb < 16; nb++)
            #pragma unroll
            for (int c = 0; c < 4; c++) acc[mt][nb][c] = 0.f;

    const uint32_t rowW = bBase + (uint32_t)((((lane & 7) + ((lane & 16) ? 8 : 0))) * 256);
    const uint32_t xorB = (uint32_t)((lane & 7) << 4);
    const uint32_t cB = (lane & 8) ? 16u : 0u;

    #pragma unroll
    for (int ks = 0; ks < 8; ks++) {
        uint32_t offB = ((uint32_t)(ks * 32) + cB) ^ xorB;
        uint32_t b[32];
        #pragma unroll
        for (int q = 0; q < 8; q++) ldsm4(rowW + (uint32_t)(q * 4096) + offB, b + 4 * q);
        #pragma unroll
        for (int nb = 0; nb < 16; nb++)
            #pragma unroll
            for (int mt = 0; mt < NMT; mt++)
                mma16816(acc[mt][nb], &hf[mt][4 * ks], b + 2 * nb);
    }
}

// ---- E0/E1: relu(acc + coef) -> fp16 A-fragments in registers ----
// MODE 1: coef = z*wz + bi (sC float2 = (wz,bi)) ; MODE 2: coef = b1 (sB12[].x)
template<int NMT, int MODE>
__device__ __forceinline__ void epi_cvt(const float (*acc)[16][4], uint32_t (*hf)[32],
                                        const float2* sC, const float2* sB12,
                                        const float* zl, int lane) {
    const int gc0 = 2 * (lane & 3);
    #pragma unroll
    for (int nb = 0; nb < 16; nb++) {
        const int c = 8 * nb + gc0;
        float x0, x1, za0 = 0.f, za1 = 0.f;
        if (MODE == 1) { float2 t0 = sC[c], t1 = sC[c + 1];
                         x0 = t0.y; x1 = t1.y; za0 = t0.x; za1 = t1.x; }
        else           { x0 = sB12[c].x; x1 = sB12[c + 1].x; }
        #pragma unroll
        for (int mt = 0; mt < NMT; mt++) {
            float v0 = acc[mt][nb][0], v1 = acc[mt][nb][1];
            float v2 = acc[mt][nb][2], v3 = acc[mt][nb][3];
            if (MODE == 1) {
                const float zlo = zl[2 * mt], zhi = zl[2 * mt + 1];
                v0 = fmaf(zlo, za0, v0); v1 = fmaf(zlo, za1, v1);
                v2 = fmaf(zhi, za0, v2); v3 = fmaf(zhi, za1, v3);
            }
            v0 = fmaxf(v0 + x0, 0.f); v1 = fmaxf(v1 + x1, 0.f);
            v2 = fmaxf(v2 + x0, 0.f); v3 = fmaxf(v3 + x1, 0.f);
            __half2 lo = __floats2half2_rn(v0, v1), hi = __floats2half2_rn(v2, v3);
            hf[mt][2 * nb]     = *(uint32_t*)&lo;
            hf[mt][2 * nb + 1] = *(uint32_t*)&hi;
        }
    }
}

// ==================== main kernel (NT tiles: warps [0,4NT) ) ====================
template<int NT>
__global__ __launch_bounds__(256, 1)
void gen_main(const float* __restrict__ x,  const float* __restrict__ bi,
              const float* __restrict__ Wf, const float* __restrict__ bf,
              const float* __restrict__ b1, const float* __restrict__ b2,
              float* __restrict__ out, int Bn, int baseRow)
{
    extern __shared__ char sm[];
    const int tid = threadIdx.x, lane = tid & 31, wid = tid >> 5;
    const int gr0 = lane >> 2, gc0 = 2 * (lane & 3);
    const int NMT = (NT == 2) ? 2 : 1;
    const int tileSel = (NT == 2) ? (wid >> 2) : 0;
    const int mrowT = (NT == 2) ? ((wid & 3) * 32) : (wid * 16);
    const size_t b0 = (size_t)baseRow + (size_t)blockIdx.x * (128 * NT);
    const size_t bT = b0 + (size_t)(tileSel << 7);

    const uint32_t smBase = (uint32_t)__cvta_generic_to_shared(sm);
    const uint32_t aOut = smBase + (tileSel ? OFF_OUTB : OFF_OUTA);
    char* outT = sm + (tileSel ? OFF_OUTB : OFF_OUTA);
    const uint32_t aW1 = smBase + OFF_W1, aW2 = smBase + OFF_W2;
    float2* sC0D = (float2*)(sm + OFF_C0);    // [2][128]
    float*  sWfD = (float*)(sm + OFF_WFD);    // [2][128]
    float2* sB12 = (float2*)(sm + OFF_B12);

    // ---- stage x into tiles (fp16, swizzled) ----
    const float4* xg = (const float4*)(x + b0 * 128);
    #pragma unroll
    for (int q = 0; q < 16 * NT; q++) {
        int v = (q << 8) + tid;
        float4 f = xg[v];
        int rv = v >> 5, c4 = (v & 31) << 2;
        uint32_t off = tile_off(rv & 127, c4);
        char* base = sm + ((rv >> 7) ? OFF_OUTB : OFF_OUTA);
        *(__half2*)(base + off)     = __floats2half2_rn(f.x, f.y);
        *(__half2*)(base + off + 4) = __floats2half2_rn(f.z, f.w);
    }
    // ---- stage W1/W2 + WiM(0) into WIM0 + coeffs(0) ----
    #pragma unroll
    for (int q = 0; q < 8; q++) {
        int v = (q << 8) + tid;
        ((uint4*)(sm + OFF_W1))[v] = ((const uint4*)g_W1h)[v];
        ((uint4*)(sm + OFF_W2))[v] = ((const uint4*)g_W2h)[v];
        cpa16(smBase + OFF_WIM0 + (uint32_t)(v << 4), ((const uint4*)g_WiM) + v);
    }
    asm volatile("cp.async.commit_group;");
    if (tid < 128) {
        sB12[tid] = make_float2(b1[tid], b2[tid]);
        sC0D[tid] = make_float2(g_wz[tid], bi[tid]);   // buf 0, step 0
        sWfD[tid] = Wf[tid];
    }
    asm volatile("cp.async.wait_group 0;");
    __syncthreads();

    float acc[(NT == 2) ? 2 : 1][16][4];
    uint32_t hf[(NT == 2) ? 2 : 1][32];

    for (int i = 0; i < 128; i++) {
        // S_A: WiM(i) landed in buf i&1; coeffs(i) visible; everyone past step i-1
        if (i) { asm volatile("cp.async.wait_group 0;"); __syncthreads(); }

        const uint32_t aWiMcur  = smBase + ((i & 1) ? OFF_WIM1 : OFF_WIM0);
        const uint32_t aWiMnext = smBase + ((i & 1) ? OFF_WIM0 : OFF_WIM1);
        const float2* sC0w = sC0D + ((i & 1) << 7);
        const float*  sWfw = sWfD + ((i & 1) << 7);
        const float bfi = bf[i];

        // ---- G0: acc = OUT_tile @ WiM^T (full N=128 for this warp's rows) ----
        gemm_s<(NT == 2) ? 2 : 1>(aOut, mrowT, aWiMcur, acc, lane);

        // ---- prefetch WiM(i+1) + stage coeffs(i+1): AFTER own G0, so cp.async
        //      fills overlap E0..E2 instead of the G0 LDSM window. Double-buffered
        //      WiM + the single S_A barrier make this race-free across warp drift.
        if (i < 127) {
            const uint4* src = (const uint4*)(g_WiM + (size_t)(i + 1) * 16384);
            #pragma unroll
            for (int q = 0; q < 8; q++) {
                int v = (q << 8) + tid;
                cpa16(aWiMnext + (uint32_t)(v << 4), src + v);
            }
            asm volatile("cp.async.commit_group;");
            if (tid < 128)
                sC0D[(((i + 1) & 1) << 7) + tid] =
                    make_float2(g_wz[((i + 1) << 7) + tid], bi[((i + 1) << 7) + tid]);
            else
                sWfD[(((i + 1) & 1) << 7) + tid - 128] = Wf[((i + 1) << 7) + tid - 128];
        }

        // ---- E0 (regs): h1 = relu(acc + z*wz + bi) -> hf ----
        float zl[(NT == 2) ? 4 : 2];
        {
            const float* zg = g_zT + (size_t)i * Bn + bT;
            #pragma unroll
            for (int k = 0; k < ((NT == 2) ? 4 : 2); k++)
                zl[k] = zg[mrowT + (k >> 1) * 16 + (k & 1) * 8 + gr0];
        }
        epi_cvt<(NT == 2) ? 2 : 1, 1>(acc, hf, sC0w, sB12, zl, lane);

        // ---- G1: acc = h1 @ W1^T (A from regs) ----
        gemm_r<(NT == 2) ? 2 : 1>(hf, aW1, acc, lane);
        // ---- E1 (regs): h2 = relu(acc + b1) -> hf ----
        epi_cvt<(NT == 2) ? 2 : 1, 2>(acc, hf, sC0w, sB12, zl, lane);
        // ---- G2: acc = h2 @ W2^T ----
        gemm_r<(NT == 2) ? 2 : 1>(hf, aW2, acc, lane);

        // ---- E2: o = relu(acc + b2) @ Wf + bf ; warp owns full rows ----
        float p0[(NT == 2) ? 2 : 1], p1[(NT == 2) ? 2 : 1];
        #pragma unroll
        for (int mt = 0; mt < NMT; mt++) { p0[mt] = 0.f; p1[mt] = 0.f; }
        #pragma unroll
        for (int nb = 0; nb < 16; nb++) {
            const int c = 8 * nb + gc0;
            const float wf0 = sWfw[c], wf1 = sWfw[c + 1];
            const float q0 = sB12[c].y, q1 = sB12[c + 1].y;
            #pragma unroll
            for (int mt = 0; mt < NMT; mt++) {
                p0[mt] = fmaf(fmaxf(acc[mt][nb][0] + q0, 0.f), wf0,
                         fmaf(fmaxf(acc[mt][nb][1] + q1, 0.f), wf1, p0[mt]));
                p1[mt] = fmaf(fmaxf(acc[mt][nb][2] + q0, 0.f), wf0,
                         fmaf(fmaxf(acc[mt][nb][3] + q1, 0.f), wf1, p1[mt]));
            }
        }
        #pragma unroll
        for (int mt = 0; mt < NMT; mt++) {
            p0[mt] += __shfl_xor_sync(0xffffffffu, p0[mt], 1);
            p0[mt] += __shfl_xor_sync(0xffffffffu, p0[mt], 2);
            p1[mt] += __shfl_xor_sync(0xffffffffu, p1[mt], 1);
            p1[mt] += __shfl_xor_sync(0xffffffffu, p1[mt], 2);
        }
        if ((lane & 3) == 0) {
            #pragma unroll
            for (int mt = 0; mt < NMT; mt++) {
                int r = mrowT + mt * 16 + gr0;
                float o0 = p0[mt] + bfi, o1 = p1[mt] + bfi;
                out[(bT + r) * 128 + i] = o0;
                out[(bT + r + 8) * 128 + i] = o1;
                *(__half*)(outT + tile_off(r, i)) = __float2half(o0);
                *(__half*)(outT + tile_off(r + 8, i)) = __float2half(o1);
            }
        }
        __syncwarp();   // own-row smem writes visible to own warp's next G0 ldsm
    }
}

// ---- host ----
extern "C" void kernel_launch(void* const* d_in, const int* in_sizes, int n_in,
                              void* d_out, int out_size) {
    const float* x  = (const float*)d_in[0];
    const float* z  = (const float*)d_in[1];
    const float* M  = (const float*)d_in[2];
    const float* Wi = (const float*)d_in[3];
    const float* bi = (const float*)d_in[4];
    const float* Wf = (const float*)d_in[5];
    const float* bf = (const float*)d_in[6];
    const float* W1 = (const float*)d_in[7];
    const float* b1 = (const float*)d_in[8];
    const float* W2 = (const float*)d_in[9];
    const float* b2 = (const float*)d_in[10];
    int Bn = in_sizes[0] / 128;

    cudaFuncSetAttribute(gen_main<2>, cudaFuncAttributeMaxDynamicSharedMemorySize, SMEM_TOTAL);
    cudaFuncSetAttribute(gen_main<1>, cudaFuncAttributeMaxDynamicSharedMemorySize, SMEM_TOTAL);

    prep_weights<<<130, 256>>>(Wi, M, W1, W2);
    transpose_z<<<dim3(Bn / 32, 4), dim3(32, 8)>>>(z, Bn);

    int tiles = Bn / 128;                       // 1024
    int nPair = ((tiles / 2) / 148) * 148;      // 444 (3 full waves)
    int nSingle = tiles - 2 * nPair;            // 136 (1 partial wave)
    if (nPair > 0)
        gen_main<2><<<nPair, 256, SMEM_TOTAL>>>(x, bi, Wf, bf, b1, b2, (float*)d_out, Bn, 0);
    if (nSingle > 0)
        gen_main<1><<<nSingle, 256, SMEM_TOTAL>>>(x, bi, Wf, bf, b1, b2, (float*)d_out, Bn, nPair * 256);
}

// round 15
// speedup vs baseline: 1.0323x; 1.0323x over previous
#include <cuda_runtime.h>
#include <cuda_fp16.h>
#include <cstdint>

// ---- SMEM layout (bytes) ----
#define OFF_OUTA 0
#define OFF_OUTB 32768
#define OFF_WIM0 65536
#define OFF_WIM1 98304     // used by NT==1 only (double buffer)
#define OFF_W1   131072
#define OFF_W2   163840
#define OFF_C0   196608    // float2[2][128] double-buffered (wz,bi) = 2KB
#define OFF_WFD  198656    // float[2][128] double-buffered Wf = 1KB
#define OFF_B12  199680    // float2[128] (b1,b2) = 1KB
#define SMEM_TOTAL 200704

// ---- device scratch ----
__device__ __half g_WiM[(size_t)128 * 16384];  // per-i swizzled 128x128 fp16 image
__device__ float  g_wz[128 * 128];
__device__ __half g_W1h[16384];                // swizzled image
__device__ __half g_W2h[16384];
__device__ float  g_zT[(size_t)128 * 131072];  // [i][b]

// XOR-swizzled byte offset in a 128x128 fp16 tile (row = 256B)
__host__ __device__ __forceinline__ uint32_t tile_off(int r, int c) {
    return (uint32_t)(r * 256 + ((c * 2) ^ ((r & 7) << 4)));
}

// ---- prologue kernels ----
__global__ void prep_weights(const float* __restrict__ Wi, const float* __restrict__ M,
                             const float* __restrict__ W1, const float* __restrict__ W2) {
    int i = blockIdx.x;
    if (i < 128) {
        const float* Wii = Wi + (size_t)i * 16512;   // 128*129
        for (int v = threadIdx.x; v < 16384; v += blockDim.x) {
            int j = v >> 7, k = v & 127;
            float m = (k == i) ? 0.f : M[k * 128 + i];
            g_WiM[(size_t)i * 16384 + (tile_off(j, k) >> 1)] = __float2half(Wii[j * 129 + k] * m);
        }
        for (int j = threadIdx.x; j < 128; j += blockDim.x)
            g_wz[i * 128 + j] = Wii[j * 129 + 128];
    } else if (i == 128) {
        for (int v = threadIdx.x; v < 16384; v += blockDim.x)
            g_W1h[tile_off(v >> 7, v & 127) >> 1] = __float2half(W1[v]);
    } else {
        for (int v = threadIdx.x; v < 16384; v += blockDim.x)
            g_W2h[tile_off(v >> 7, v & 127) >> 1] = __float2half(W2[v]);
    }
}

__global__ void transpose_z(const float* __restrict__ z, int Bn) {
    __shared__ float t[32][33];
    int b0 = blockIdx.x * 32, i0 = blockIdx.y * 32;
    #pragma unroll
    for (int r = threadIdx.y; r < 32; r += 8)
        t[r][threadIdx.x] = z[(size_t)(b0 + r) * 128 + i0 + threadIdx.x];
    __syncthreads();
    #pragma unroll
    for (int r = threadIdx.y; r < 32; r += 8)
        g_zT[(size_t)(i0 + r) * Bn + b0 + threadIdx.x] = t[threadIdx.x][r];
}

// ---- mma helpers ----
__device__ __forceinline__ void ldsm4(uint32_t addr, uint32_t* r) {
    asm volatile("ldmatrix.sync.aligned.m8n8.x4.shared.b16 {%0,%1,%2,%3},[%4];"
        : "=r"(r[0]), "=r"(r[1]), "=r"(r[2]), "=r"(r[3]) : "r"(addr));
}
__device__ __forceinline__ void mma16816(float* c, const uint32_t* a, const uint32_t* b) {
    asm volatile("mma.sync.aligned.m16n8k16.row.col.f32.f16.f16.f32 "
        "{%0,%1,%2,%3},{%4,%5,%6,%7},{%8,%9},{%0,%1,%2,%3};"
        : "+f"(c[0]), "+f"(c[1]), "+f"(c[2]), "+f"(c[3])
        : "r"(a[0]), "r"(a[1]), "r"(a[2]), "r"(a[3]), "r"(b[0]), "r"(b[1]));
}
__device__ __forceinline__ void cpa16(uint32_t s, const void* g) {
    asm volatile("cp.async.cg.shared.global [%0],[%1],16;" :: "r"(s), "l"(g));
}

// ---- GEMM over full N=128, A from smem (G0). Warp rows: mrowT..mrowT+16*NMT ----
template<int NMT>
__device__ __forceinline__ void gemm_s(uint32_t aTile, int mrowT, uint32_t bBase,
                                       float (*acc)[16][4], int lane) {
    #pragma unroll
    for (int mt = 0; mt < NMT; mt++)
        #pragma unroll
        for (int nb = 0; nb < 16; nb++)
            #pragma unroll
            for (int c = 0; c < 4; c++) acc[mt][nb][c] = 0.f;

    const uint32_t xorA = (uint32_t)((lane & 7) << 4);
    const uint32_t cA = (lane & 16) ? 16u : 0u;
    uint32_t rowA[NMT];
    #pragma unroll
    for (int mt = 0; mt < NMT; mt++)
        rowA[mt] = aTile + (uint32_t)((mrowT + mt * 16 + (lane & 15)) * 256);
    const uint32_t rowW = bBase + (uint32_t)((((lane & 7) + ((lane & 16) ? 8 : 0))) * 256);
    const uint32_t xorB = (uint32_t)((lane & 7) << 4);
    const uint32_t cB = (lane & 8) ? 16u : 0u;

    #pragma unroll
    for (int ks = 0; ks < 8; ks++) {
        uint32_t offA = ((uint32_t)(ks * 32) + cA) ^ xorA;
        uint32_t offB = ((uint32_t)(ks * 32) + cB) ^ xorB;
        uint32_t a[NMT][4], b[32];
        #pragma unroll
        for (int mt = 0; mt < NMT; mt++) ldsm4(rowA[mt] + offA, a[mt]);
        #pragma unroll
        for (int q = 0; q < 8; q++) ldsm4(rowW + (uint32_t)(q * 4096) + offB, b + 4 * q);
        #pragma unroll
        for (int nb = 0; nb < 16; nb++)
            #pragma unroll
            for (int mt = 0; mt < NMT; mt++)
                mma16816(acc[mt][nb], a[mt], b + 2 * nb);
    }
}

// ---- GEMM over full N=128, A from registers (hf: C->A fragment identity) ----
template<int NMT>
__device__ __forceinline__ void gemm_r(const uint32_t (*hf)[32], uint32_t bBase,
                                       float (*acc)[16][4], int lane) {
    #pragma unroll
    for (int mt = 0; mt < NMT; mt++)
        #pragma unroll
        for (int nb = 0; nb < 16; nb++)
            #pragma unroll
            for (int c = 0; c < 4; c++) acc[mt][nb][c] = 0.f;

    const uint32_t rowW = bBase + (uint32_t)((((lane & 7) + ((lane & 16) ? 8 : 0))) * 256);
    const uint32_t xorB = (uint32_t)((lane & 7) << 4);
    const uint32_t cB = (lane & 8) ? 16u : 0u;

    #pragma unroll
    for (int ks = 0; ks < 8; ks++) {
        uint32_t offB = ((uint32_t)(ks * 32) + cB) ^ xorB;
        uint32_t b[32];
        #pragma unroll
        for (int q = 0; q < 8; q++) ldsm4(rowW + (uint32_t)(q * 4096) + offB, b + 4 * q);
        #pragma unroll
        for (int nb = 0; nb < 16; nb++)
            #pragma unroll
            for (int mt = 0; mt < NMT; mt++)
                mma16816(acc[mt][nb], &hf[mt][4 * ks], b + 2 * nb);
    }
}

// ---- E0/E1: relu(acc + coef) -> fp16 A-fragments in registers ----
// MODE 1: coef = z*wz + bi (sC float2 = (wz,bi)) ; MODE 2: coef = b1 (sB12[].x)
template<int NMT, int MODE>
__device__ __forceinline__ void epi_cvt(const float (*acc)[16][4], uint32_t (*hf)[32],
                                        const float2* sC, const float2* sB12,
                                        const float* zl, int lane) {
    const int gc0 = 2 * (lane & 3);
    #pragma unroll
    for (int nb = 0; nb < 16; nb++) {
        const int c = 8 * nb + gc0;
        float x0, x1, za0 = 0.f, za1 = 0.f;
        if (MODE == 1) { float2 t0 = sC[c], t1 = sC[c + 1];
                         x0 = t0.y; x1 = t1.y; za0 = t0.x; za1 = t1.x; }
        else           { x0 = sB12[c].x; x1 = sB12[c + 1].x; }
        #pragma unroll
        for (int mt = 0; mt < NMT; mt++) {
            float v0 = acc[mt][nb][0], v1 = acc[mt][nb][1];
            float v2 = acc[mt][nb][2], v3 = acc[mt][nb][3];
            if (MODE == 1) {
                const float zlo = zl[2 * mt], zhi = zl[2 * mt + 1];
                v0 = fmaf(zlo, za0, v0); v1 = fmaf(zlo, za1, v1);
                v2 = fmaf(zhi, za0, v2); v3 = fmaf(zhi, za1, v3);
            }
            v0 = fmaxf(v0 + x0, 0.f); v1 = fmaxf(v1 + x1, 0.f);
            v2 = fmaxf(v2 + x0, 0.f); v3 = fmaxf(v3 + x1, 0.f);
            __half2 lo = __floats2half2_rn(v0, v1), hi = __floats2half2_rn(v2, v3);
            hf[mt][2 * nb]     = *(uint32_t*)&lo;
            hf[mt][2 * nb + 1] = *(uint32_t*)&hi;
        }
    }
}

// ==================== main kernel ====================
// NT==2: R12 schedule — single WiM buffer, S_B barrier after G0, prefetch after S_B.
// NT==1: R13 schedule — double WiM buffer, prefetch at step top, one barrier.
template<int NT>
__global__ __launch_bounds__(256, 1)
void gen_main(const float* __restrict__ x,  const float* __restrict__ bi,
              const float* __restrict__ Wf, const float* __restrict__ bf,
              const float* __restrict__ b1, const float* __restrict__ b2,
              float* __restrict__ out, int Bn, int baseRow)
{
    extern __shared__ char sm[];
    const int tid = threadIdx.x, lane = tid & 31, wid = tid >> 5;
    const int gr0 = lane >> 2, gc0 = 2 * (lane & 3);
    const int NMT = (NT == 2) ? 2 : 1;
    const int tileSel = (NT == 2) ? (wid >> 2) : 0;
    const int mrowT = (NT == 2) ? ((wid & 3) * 32) : (wid * 16);
    const size_t b0 = (size_t)baseRow + (size_t)blockIdx.x * (128 * NT);
    const size_t bT = b0 + (size_t)(tileSel << 7);

    const uint32_t smBase = (uint32_t)__cvta_generic_to_shared(sm);
    const uint32_t aOut = smBase + (tileSel ? OFF_OUTB : OFF_OUTA);
    char* outT = sm + (tileSel ? OFF_OUTB : OFF_OUTA);
    const uint32_t aW1 = smBase + OFF_W1, aW2 = smBase + OFF_W2;
    float2* sC0D = (float2*)(sm + OFF_C0);    // [2][128]
    float*  sWfD = (float*)(sm + OFF_WFD);    // [2][128]
    float2* sB12 = (float2*)(sm + OFF_B12);

    // ---- stage x into tiles (fp16, swizzled) ----
    const float4* xg = (const float4*)(x + b0 * 128);
    #pragma unroll
    for (int q = 0; q < 16 * NT; q++) {
        int v = (q << 8) + tid;
        float4 f = xg[v];
        int rv = v >> 5, c4 = (v & 31) << 2;
        uint32_t off = tile_off(rv & 127, c4);
        char* base = sm + ((rv >> 7) ? OFF_OUTB : OFF_OUTA);
        *(__half2*)(base + off)     = __floats2half2_rn(f.x, f.y);
        *(__half2*)(base + off + 4) = __floats2half2_rn(f.z, f.w);
    }
    // ---- stage W1/W2 + WiM(0) into WIM0 + coeffs(0) ----
    #pragma unroll
    for (int q = 0; q < 8; q++) {
        int v = (q << 8) + tid;
        ((uint4*)(sm + OFF_W1))[v] = ((const uint4*)g_W1h)[v];
        ((uint4*)(sm + OFF_W2))[v] = ((const uint4*)g_W2h)[v];
        cpa16(smBase + OFF_WIM0 + (uint32_t)(v << 4), ((const uint4*)g_WiM) + v);
    }
    asm volatile("cp.async.commit_group;");
    if (tid < 128) {
        sB12[tid] = make_float2(b1[tid], b2[tid]);
        sC0D[tid] = make_float2(g_wz[tid], bi[tid]);   // buf 0, step 0
        sWfD[tid] = Wf[tid];
    }
    asm volatile("cp.async.wait_group 0;");
    __syncthreads();

    float acc[(NT == 2) ? 2 : 1][16][4];
    uint32_t hf[(NT == 2) ? 2 : 1][32];

    for (int i = 0; i < 128; i++) {
        // S_A: WiM(i) landed; coeffs(i) visible; everyone past step i-1
        if (i) { asm volatile("cp.async.wait_group 0;"); __syncthreads(); }

        const uint32_t aWiMcur = (NT == 2) ? (smBase + OFF_WIM0)
                               : (smBase + ((i & 1) ? OFF_WIM1 : OFF_WIM0));
        const float2* sC0w = sC0D + ((i & 1) << 7);
        const float*  sWfw = sWfD + ((i & 1) << 7);
        const float bfi = bf[i];

        // stage coeffs(i+1) at top (both schedules; R12 did this at top too)
        if (i < 127) {
            if (tid < 128)
                sC0D[(((i + 1) & 1) << 7) + tid] =
                    make_float2(g_wz[((i + 1) << 7) + tid], bi[((i + 1) << 7) + tid]);
            else
                sWfD[(((i + 1) & 1) << 7) + tid - 128] = Wf[((i + 1) << 7) + tid - 128];
            if (NT == 1) {
                // R13 schedule: prefetch WiM(i+1) into other buffer at step top
                const uint32_t aWiMnext = smBase + ((i & 1) ? OFF_WIM0 : OFF_WIM1);
                const uint4* src = (const uint4*)(g_WiM + (size_t)(i + 1) * 16384);
                #pragma unroll
                for (int q = 0; q < 8; q++) {
                    int v = (q << 8) + tid;
                    cpa16(aWiMnext + (uint32_t)(v << 4), src + v);
                }
                asm volatile("cp.async.commit_group;");
            }
        }

        // ---- G0: acc = OUT_tile @ WiM^T ----
        gemm_s<(NT == 2) ? 2 : 1>(aOut, mrowT, aWiMcur, acc, lane);

        if (NT == 2) {
            __syncthreads();                       // S_B: all WiM reads done
            if (i < 127) {                         // R12: prefetch into SAME buffer
                const uint4* src = (const uint4*)(g_WiM + (size_t)(i + 1) * 16384);
                #pragma unroll
                for (int q = 0; q < 8; q++) {
                    int v = (q << 8) + tid;
                    cpa16(smBase + OFF_WIM0 + (uint32_t)(v << 4), src + v);
                }
                asm volatile("cp.async.commit_group;");
            }
        }

        // ---- E0 (regs): h1 = relu(acc + z*wz + bi) -> hf ----
        float zl[(NT == 2) ? 4 : 2];
        {
            const float* zg = g_zT + (size_t)i * Bn + bT;
            #pragma unroll
            for (int k = 0; k < ((NT == 2) ? 4 : 2); k++)
                zl[k] = zg[mrowT + (k >> 1) * 16 + (k & 1) * 8 + gr0];
        }
        epi_cvt<(NT == 2) ? 2 : 1, 1>(acc, hf, sC0w, sB12, zl, lane);

        // ---- G1: acc = h1 @ W1^T (A from regs) ----
        gemm_r<(NT == 2) ? 2 : 1>(hf, aW1, acc, lane);
        // ---- E1 (regs): h2 = relu(acc + b1) -> hf ----
        epi_cvt<(NT == 2) ? 2 : 1, 2>(acc, hf, sC0w, sB12, zl, lane);
        // ---- G2: acc = h2 @ W2^T ----
        gemm_r<(NT == 2) ? 2 : 1>(hf, aW2, acc, lane);

        // ---- E2: o = relu(acc + b2) @ Wf + bf ; warp owns full rows ----
        float p0[(NT == 2) ? 2 : 1], p1[(NT == 2) ? 2 : 1];
        #pragma unroll
        for (int mt = 0; mt < NMT; mt++) { p0[mt] = 0.f; p1[mt] = 0.f; }
        #pragma unroll
        for (int nb = 0; nb < 16; nb++) {
            const int c = 8 * nb + gc0;
            const float wf0 = sWfw[c], wf1 = sWfw[c + 1];
            const float q0 = sB12[c].y, q1 = sB12[c + 1].y;
            #pragma unroll
            for (int mt = 0; mt < NMT; mt++) {
                p0[mt] = fmaf(fmaxf(acc[mt][nb][0] + q0, 0.f), wf0,
                         fmaf(fmaxf(acc[mt][nb][1] + q1, 0.f), wf1, p0[mt]));
                p1[mt] = fmaf(fmaxf(acc[mt][nb][2] + q0, 0.f), wf0,
                         fmaf(fmaxf(acc[mt][nb][3] + q1, 0.f), wf1, p1[mt]));
            }
        }
        #pragma unroll
        for (int mt = 0; mt < NMT; mt++) {
            p0[mt] += __shfl_xor_sync(0xffffffffu, p0[mt], 1);
            p0[mt] += __shfl_xor_sync(0xffffffffu, p0[mt], 2);
            p1[mt] += __shfl_xor_sync(0xffffffffu, p1[mt], 1);
            p1[mt] += __shfl_xor_sync(0xffffffffu, p1[mt], 2);
        }
        if ((lane & 3) == 0) {
            #pragma unroll
            for (int mt = 0; mt < NMT; mt++) {
                int r = mrowT + mt * 16 + gr0;
                float o0 = p0[mt] + bfi, o1 = p1[mt] + bfi;
                out[(bT + r) * 128 + i] = o0;
                out[(bT + r + 8) * 128 + i] = o1;
                *(__half*)(outT + tile_off(r, i)) = __float2half(o0);
                *(__half*)(outT + tile_off(r + 8, i)) = __float2half(o1);
            }
        }
        __syncwarp();   // own-row smem writes visible to own warp's next G0 ldsm
    }
}

// ---- host ----
extern "C" void kernel_launch(void* const* d_in, const int* in_sizes, int n_in,
                              void* d_out, int out_size) {
    const float* x  = (const float*)d_in[0];
    const float* z  = (const float*)d_in[1];
    const float* M  = (const float*)d_in[2];
    const float* Wi = (const float*)d_in[3];
    const float* bi = (const float*)d_in[4];
    const float* Wf = (const float*)d_in[5];
    const float* bf = (const float*)d_in[6];
    const float* W1 = (const float*)d_in[7];
    const float* b1 = (const float*)d_in[8];
    const float* W2 = (const float*)d_in[9];
    const float* b2 = (const float*)d_in[10];
    int Bn = in_sizes[0] / 128;

    cudaFuncSetAttribute(gen_main<2>, cudaFuncAttributeMaxDynamicSharedMemorySize, SMEM_TOTAL);
    cudaFuncSetAttribute(gen_main<1>, cudaFuncAttributeMaxDynamicSharedMemorySize, SMEM_TOTAL);

    prep_weights<<<130, 256>>>(Wi, M, W1, W2);
    transpose_z<<<dim3(Bn / 32, 4), dim3(32, 8)>>>(z, Bn);

    int tiles = Bn / 128;                       // 1024
    int nPair = ((tiles / 2) / 148) * 148;      // 444 (3 full waves)
    int nSingle = tiles - 2 * nPair;            // 136 (1 partial wave)
    if (nPair > 0)
        gen_main<2><<<nPair, 256, SMEM_TOTAL>>>(x, bi, Wf, bf, b1, b2, (float*)d_out, Bn, 0);
    if (nSingle > 0)
        gen_main<1><<<nSingle, 256, SMEM_TOTAL>>>(x, bi, Wf, bf, b1, b2, (float*)d_out, Bn, nPair * 256);
}

// round 16
// speedup vs baseline: 1.0837x; 1.0498x over previous
#include <cuda_runtime.h>
#include <cuda_fp16.h>
#include <cstdint>

// ---- SMEM layout (bytes) ----
#define OFF_OUTA 0
#define OFF_OUTB 32768
#define OFF_WIM0 65536
#define OFF_WIM1 98304     // used by NT==1 only (double buffer)
#define OFF_W1   131072
#define OFF_W2   163840
#define OFF_CH   196608    // uint2[2][64] (wz2,bi2 half2 pairs) double-buffered = 1KB
#define OFF_B1H  197632    // uint32[64] half2 b1 = 256B
#define OFF_WBD  197888    // float2[2][128] (wf,b2) double-buffered = 2KB
#define SMEM_TOTAL 199936

// ---- device scratch ----
__device__ __half g_WiM[(size_t)128 * 16384];  // per-i swizzled 128x128 fp16 image
__device__ float  g_wz[128 * 128];
__device__ __half g_W1h[16384];                // swizzled image
__device__ __half g_W2h[16384];
__device__ float  g_zT[(size_t)128 * 131072];  // [i][b]

// XOR-swizzled byte offset in a 128x128 fp16 tile (row = 256B)
__host__ __device__ __forceinline__ uint32_t tile_off(int r, int c) {
    return (uint32_t)(r * 256 + ((c * 2) ^ ((r & 7) << 4)));
}

// ---- prologue kernels ----
__global__ void prep_weights(const float* __restrict__ Wi, const float* __restrict__ M,
                             const float* __restrict__ W1, const float* __restrict__ W2) {
    int i = blockIdx.x;
    if (i < 128) {
        const float* Wii = Wi + (size_t)i * 16512;   // 128*129
        for (int v = threadIdx.x; v < 16384; v += blockDim.x) {
            int j = v >> 7, k = v & 127;
            float m = (k == i) ? 0.f : M[k * 128 + i];
            g_WiM[(size_t)i * 16384 + (tile_off(j, k) >> 1)] = __float2half(Wii[j * 129 + k] * m);
        }
        for (int j = threadIdx.x; j < 128; j += blockDim.x)
            g_wz[i * 128 + j] = Wii[j * 129 + 128];
    } else if (i == 128) {
        for (int v = threadIdx.x; v < 16384; v += blockDim.x)
            g_W1h[tile_off(v >> 7, v & 127) >> 1] = __float2half(W1[v]);
    } else {
        for (int v = threadIdx.x; v < 16384; v += blockDim.x)
            g_W2h[tile_off(v >> 7, v & 127) >> 1] = __float2half(W2[v]);
    }
}

__global__ void transpose_z(const float* __restrict__ z, int Bn) {
    __shared__ float t[32][33];
    int b0 = blockIdx.x * 32, i0 = blockIdx.y * 32;
    #pragma unroll
    for (int r = threadIdx.y; r < 32; r += 8)
        t[r][threadIdx.x] = z[(size_t)(b0 + r) * 128 + i0 + threadIdx.x];
    __syncthreads();
    #pragma unroll
    for (int r = threadIdx.y; r < 32; r += 8)
        g_zT[(size_t)(i0 + r) * Bn + b0 + threadIdx.x] = t[threadIdx.x][r];
}

// ---- mma helpers ----
__device__ __forceinline__ void ldsm4(uint32_t addr, uint32_t* r) {
    asm volatile("ldmatrix.sync.aligned.m8n8.x4.shared.b16 {%0,%1,%2,%3},[%4];"
        : "=r"(r[0]), "=r"(r[1]), "=r"(r[2]), "=r"(r[3]) : "r"(addr));
}
__device__ __forceinline__ void mma16816(float* c, const uint32_t* a, const uint32_t* b) {
    asm volatile("mma.sync.aligned.m16n8k16.row.col.f32.f16.f16.f32 "
        "{%0,%1,%2,%3},{%4,%5,%6,%7},{%8,%9},{%0,%1,%2,%3};"
        : "+f"(c[0]), "+f"(c[1]), "+f"(c[2]), "+f"(c[3])
        : "r"(a[0]), "r"(a[1]), "r"(a[2]), "r"(a[3]), "r"(b[0]), "r"(b[1]));
}
__device__ __forceinline__ void cpa16(uint32_t s, const void* g) {
    asm volatile("cp.async.cg.shared.global [%0],[%1],16;" :: "r"(s), "l"(g));
}

// ---- GEMM over full N=128, A from smem (G0). Warp rows: mrowT..mrowT+16*NMT ----
template<int NMT>
__device__ __forceinline__ void gemm_s(uint32_t aTile, int mrowT, uint32_t bBase,
                                       float (*acc)[16][4], int lane) {
    #pragma unroll
    for (int mt = 0; mt < NMT; mt++)
        #pragma unroll
        for (int nb = 0; nb < 16; nb++)
            #pragma unroll
            for (int c = 0; c < 4; c++) acc[mt][nb][c] = 0.f;

    const uint32_t xorA = (uint32_t)((lane & 7) << 4);
    const uint32_t cA = (lane & 16) ? 16u : 0u;
    uint32_t rowA[NMT];
    #pragma unroll
    for (int mt = 0; mt < NMT; mt++)
        rowA[mt] = aTile + (uint32_t)((mrowT + mt * 16 + (lane & 15)) * 256);
    const uint32_t rowW = bBase + (uint32_t)((((lane & 7) + ((lane & 16) ? 8 : 0))) * 256);
    const uint32_t xorB = (uint32_t)((lane & 7) << 4);
    const uint32_t cB = (lane & 8) ? 16u : 0u;

    #pragma unroll
    for (int ks = 0; ks < 8; ks++) {
        uint32_t offA = ((uint32_t)(ks * 32) + cA) ^ xorA;
        uint32_t offB = ((uint32_t)(ks * 32) + cB) ^ xorB;
        uint32_t a[NMT][4], b[32];
        #pragma unroll
        for (int mt = 0; mt < NMT; mt++) ldsm4(rowA[mt] + offA, a[mt]);
        #pragma unroll
        for (int q = 0; q < 8; q++) ldsm4(rowW + (uint32_t)(q * 4096) + offB, b + 4 * q);
        #pragma unroll
        for (int nb = 0; nb < 16; nb++)
            #pragma unroll
            for (int mt = 0; mt < NMT; mt++)
                mma16816(acc[mt][nb], a[mt], b + 2 * nb);
    }
}

// ---- GEMM over full N=128, A from registers (hf: C->A fragment identity) ----
template<int NMT>
__device__ __forceinline__ void gemm_r(const uint32_t (*hf)[32], uint32_t bBase,
                                       float (*acc)[16][4], int lane) {
    #pragma unroll
    for (int mt = 0; mt < NMT; mt++)
        #pragma unroll
        for (int nb = 0; nb < 16; nb++)
            #pragma unroll
            for (int c = 0; c < 4; c++) acc[mt][nb][c] = 0.f;

    const uint32_t rowW = bBase + (uint32_t)((((lane & 7) + ((lane & 16) ? 8 : 0))) * 256);
    const uint32_t xorB = (uint32_t)((lane & 7) << 4);
    const uint32_t cB = (lane & 8) ? 16u : 0u;

    #pragma unroll
    for (int ks = 0; ks < 8; ks++) {
        uint32_t offB = ((uint32_t)(ks * 32) + cB) ^ xorB;
        uint32_t b[32];
        #pragma unroll
        for (int q = 0; q < 8; q++) ldsm4(rowW + (uint32_t)(q * 4096) + offB, b + 4 * q);
        #pragma unroll
        for (int nb = 0; nb < 16; nb++)
            #pragma unroll
            for (int mt = 0; mt < NMT; mt++)
                mma16816(acc[mt][nb], &hf[mt][4 * ks], b + 2 * nb);
    }
}

// ---- E0/E1: packed fp16 epilogue -> A-fragments in registers ----
// MODE 1: h = relu(hfma2(z2, wz2, acc_h) + bi2) ; MODE 2: h = relu(acc_h + b1_2)
template<int NMT, int MODE>
__device__ __forceinline__ void epi_h(const float (*acc)[16][4], uint32_t (*hf)[32],
                                      const uint2* sCH, const uint32_t* sB1H,
                                      const __half2* zz, int lane) {
    const int lq = lane & 3;
    const __half2 zero2 = __floats2half2_rn(0.f, 0.f);
    #pragma unroll
    for (int nb = 0; nb < 16; nb++) {
        __half2 wz2, bi2;
        if (MODE == 1) {
            uint2 wb = sCH[4 * nb + lq];
            wz2 = *(__half2*)&wb.x;
            bi2 = *(__half2*)&wb.y;
        } else {
            uint32_t b1u = sB1H[4 * nb + lq];
            bi2 = *(__half2*)&b1u;
        }
        #pragma unroll
        for (int mt = 0; mt < NMT; mt++) {
            __half2 a01 = __floats2half2_rn(acc[mt][nb][0], acc[mt][nb][1]);
            __half2 a23 = __floats2half2_rn(acc[mt][nb][2], acc[mt][nb][3]);
            __half2 t01, t23;
            if (MODE == 1) {
                t01 = __hmax2(__hadd2(__hfma2(zz[2 * mt],     wz2, a01), bi2), zero2);
                t23 = __hmax2(__hadd2(__hfma2(zz[2 * mt + 1], wz2, a23), bi2), zero2);
            } else {
                t01 = __hmax2(__hadd2(a01, bi2), zero2);
                t23 = __hmax2(__hadd2(a23, bi2), zero2);
            }
            hf[mt][2 * nb]     = *(uint32_t*)&t01;
            hf[mt][2 * nb + 1] = *(uint32_t*)&t23;
        }
    }
}

// ==================== main kernel ====================
// NT==2: R12 schedule — single WiM buffer, S_B barrier after G0, prefetch after S_B.
// NT==1: R13 schedule — double WiM buffer, prefetch at step top, one barrier.
template<int NT>
__global__ __launch_bounds__(256, 1)
void gen_main(const float* __restrict__ x,  const float* __restrict__ bi,
              const float* __restrict__ Wf, const float* __restrict__ bf,
              const float* __restrict__ b1, const float* __restrict__ b2,
              float* __restrict__ out, int Bn, int baseRow)
{
    extern __shared__ char sm[];
    const int tid = threadIdx.x, lane = tid & 31, wid = tid >> 5;
    const int gr0 = lane >> 2, gc0 = 2 * (lane & 3);
    const int NMT = (NT == 2) ? 2 : 1;
    const int tileSel = (NT == 2) ? (wid >> 2) : 0;
    const int mrowT = (NT == 2) ? ((wid & 3) * 32) : (wid * 16);
    const size_t b0 = (size_t)baseRow + (size_t)blockIdx.x * (128 * NT);
    const size_t bT = b0 + (size_t)(tileSel << 7);

    const uint32_t smBase = (uint32_t)__cvta_generic_to_shared(sm);
    const uint32_t aOut = smBase + (tileSel ? OFF_OUTB : OFF_OUTA);
    char* outT = sm + (tileSel ? OFF_OUTB : OFF_OUTA);
    const uint32_t aW1 = smBase + OFF_W1, aW2 = smBase + OFF_W2;
    uint2*    sCHD = (uint2*)(sm + OFF_CH);     // [2][64] (wz2,bi2)
    uint32_t* sB1H = (uint32_t*)(sm + OFF_B1H); // [64] b1 half2
    float2*   sWBD = (float2*)(sm + OFF_WBD);   // [2][128] (wf,b2)

    // ---- stage x into tiles (fp16, swizzled) ----
    const float4* xg = (const float4*)(x + b0 * 128);
    #pragma unroll
    for (int q = 0; q < 16 * NT; q++) {
        int v = (q << 8) + tid;
        float4 f = xg[v];
        int rv = v >> 5, c4 = (v & 31) << 2;
        uint32_t off = tile_off(rv & 127, c4);
        char* base = sm + ((rv >> 7) ? OFF_OUTB : OFF_OUTA);
        *(__half2*)(base + off)     = __floats2half2_rn(f.x, f.y);
        *(__half2*)(base + off + 4) = __floats2half2_rn(f.z, f.w);
    }
    // ---- stage W1/W2 + WiM(0) into WIM0 + coeffs(0) ----
    #pragma unroll
    for (int q = 0; q < 8; q++) {
        int v = (q << 8) + tid;
        ((uint4*)(sm + OFF_W1))[v] = ((const uint4*)g_W1h)[v];
        ((uint4*)(sm + OFF_W2))[v] = ((const uint4*)g_W2h)[v];
        cpa16(smBase + OFF_WIM0 + (uint32_t)(v << 4), ((const uint4*)g_WiM) + v);
    }
    asm volatile("cp.async.commit_group;");
    if (tid < 64) {
        int c = 2 * tid;
        __half2 wz2 = __floats2half2_rn(g_wz[c], g_wz[c + 1]);
        __half2 bi2 = __floats2half2_rn(bi[c], bi[c + 1]);
        uint2 u; u.x = *(uint32_t*)&wz2; u.y = *(uint32_t*)&bi2;
        sCHD[tid] = u;
        __half2 b12 = __floats2half2_rn(b1[c], b1[c + 1]);
        sB1H[tid] = *(uint32_t*)&b12;
    } else if (tid < 192) {
        int c = tid - 64;
        sWBD[c] = make_float2(Wf[c], b2[c]);
    }
    asm volatile("cp.async.wait_group 0;");
    __syncthreads();

    float acc[(NT == 2) ? 2 : 1][16][4];
    uint32_t hf[(NT == 2) ? 2 : 1][32];

    for (int i = 0; i < 128; i++) {
        // S_A: WiM(i) landed; coeffs(i) visible; everyone past step i-1
        if (i) { asm volatile("cp.async.wait_group 0;"); __syncthreads(); }

        const uint32_t aWiMcur = (NT == 2) ? (smBase + OFF_WIM0)
                               : (smBase + ((i & 1) ? OFF_WIM1 : OFF_WIM0));
        const uint2*  sCHw = sCHD + ((i & 1) << 6);
        const float2* sWBw = sWBD + ((i & 1) << 7);
        const float bfi = bf[i];

        // stage coeffs(i+1) at top
        if (i < 127) {
            if (tid < 64) {
                int c = 2 * tid;
                __half2 wz2 = __floats2half2_rn(g_wz[((i + 1) << 7) + c],
                                                g_wz[((i + 1) << 7) + c + 1]);
                __half2 bi2 = __floats2half2_rn(bi[((i + 1) << 7) + c],
                                                bi[((i + 1) << 7) + c + 1]);
                uint2 u; u.x = *(uint32_t*)&wz2; u.y = *(uint32_t*)&bi2;
                sCHD[(((i + 1) & 1) << 6) + tid] = u;
            } else if (tid < 192) {
                int c = tid - 64;
                sWBD[(((i + 1) & 1) << 7) + c] = make_float2(Wf[((i + 1) << 7) + c], b2[c]);
            }
            if (NT == 1) {
                // R13 schedule: prefetch WiM(i+1) into other buffer at step top
                const uint32_t aWiMnext = smBase + ((i & 1) ? OFF_WIM0 : OFF_WIM1);
                const uint4* src = (const uint4*)(g_WiM + (size_t)(i + 1) * 16384);
                #pragma unroll
                for (int q = 0; q < 8; q++) {
                    int v = (q << 8) + tid;
                    cpa16(aWiMnext + (uint32_t)(v << 4), src + v);
                }
                asm volatile("cp.async.commit_group;");
            }
        }

        // ---- G0: acc = OUT_tile @ WiM^T ----
        gemm_s<(NT == 2) ? 2 : 1>(aOut, mrowT, aWiMcur, acc, lane);

        if (NT == 2) {
            __syncthreads();                       // S_B: all WiM reads done
            if (i < 127) {                         // R12: prefetch into SAME buffer
                const uint4* src = (const uint4*)(g_WiM + (size_t)(i + 1) * 16384);
                #pragma unroll
                for (int q = 0; q < 8; q++) {
                    int v = (q << 8) + tid;
                    cpa16(smBase + OFF_WIM0 + (uint32_t)(v << 4), src + v);
                }
                asm volatile("cp.async.commit_group;");
            }
        }

        // ---- E0 (packed fp16): h1 = relu(z*wz + acc + bi) -> hf ----
        __half2 zz[(NT == 2) ? 4 : 2];
        {
            const float* zg = g_zT + (size_t)i * Bn + bT;
            #pragma unroll
            for (int k = 0; k < ((NT == 2) ? 4 : 2); k++) {
                float zv = zg[mrowT + (k >> 1) * 16 + (k & 1) * 8 + gr0];
                zz[k] = __half2half2(__float2half_rn(zv));
            }
        }
        epi_h<(NT == 2) ? 2 : 1, 1>(acc, hf, sCHw, sB1H, zz, lane);

        // ---- G1: acc = h1 @ W1^T (A from regs) ----
        gemm_r<(NT == 2) ? 2 : 1>(hf, aW1, acc, lane);
        // ---- E1 (packed fp16): h2 = relu(acc + b1) -> hf ----
        epi_h<(NT == 2) ? 2 : 1, 2>(acc, hf, sCHw, sB1H, zz, lane);
        // ---- G2: acc = h2 @ W2^T ----
        gemm_r<(NT == 2) ? 2 : 1>(hf, aW2, acc, lane);

        // ---- E2 (fp32): o = relu(acc + b2) @ Wf + bf ; warp owns full rows ----
        float p0[(NT == 2) ? 2 : 1], p1[(NT == 2) ? 2 : 1];
        #pragma unroll
        for (int mt = 0; mt < NMT; mt++) { p0[mt] = 0.f; p1[mt] = 0.f; }
        #pragma unroll
        for (int nb = 0; nb < 16; nb++) {
            const int c = 8 * nb + gc0;
            float2 wb0 = sWBw[c], wb1 = sWBw[c + 1];
            #pragma unroll
            for (int mt = 0; mt < NMT; mt++) {
                p0[mt] = fmaf(fmaxf(acc[mt][nb][0] + wb0.y, 0.f), wb0.x,
                         fmaf(fmaxf(acc[mt][nb][1] + wb1.y, 0.f), wb1.x, p0[mt]));
                p1[mt] = fmaf(fmaxf(acc[mt][nb][2] + wb0.y, 0.f), wb0.x,
                         fmaf(fmaxf(acc[mt][nb][3] + wb1.y, 0.f), wb1.x, p1[mt]));
            }
        }
        #pragma unroll
        for (int mt = 0; mt < NMT; mt++) {
            p0[mt] += __shfl_xor_sync(0xffffffffu, p0[mt], 1);
            p0[mt] += __shfl_xor_sync(0xffffffffu, p0[mt], 2);
            p1[mt] += __shfl_xor_sync(0xffffffffu, p1[mt], 1);
            p1[mt] += __shfl_xor_sync(0xffffffffu, p1[mt], 2);
        }
        if ((lane & 3) == 0) {
            #pragma unroll
            for (int mt = 0; mt < NMT; mt++) {
                int r = mrowT + mt * 16 + gr0;
                float o0 = p0[mt] + bfi, o1 = p1[mt] + bfi;
                out[(bT + r) * 128 + i] = o0;
                out[(bT + r + 8) * 128 + i] = o1;
                *(__half*)(outT + tile_off(r, i)) = __float2half(o0);
                *(__half*)(outT + tile_off(r + 8, i)) = __float2half(o1);
            }
        }
        __syncwarp();   // own-row smem writes visible to own warp's next G0 ldsm
    }
}

// ---- host ----
extern "C" void kernel_launch(void* const* d_in, const int* in_sizes, int n_in,
                              void* d_out, int out_size) {
    const float* x  = (const float*)d_in[0];
    const float* z  = (const float*)d_in[1];
    const float* M  = (const float*)d_in[2];
    const float* Wi = (const float*)d_in[3];
    const float* bi = (const float*)d_in[4];
    const float* Wf = (const float*)d_in[5];
    const float* bf = (const float*)d_in[6];
    const float* W1 = (const float*)d_in[7];
    const float* b1 = (const float*)d_in[8];
    const float* W2 = (const float*)d_in[9];
    const float* b2 = (const float*)d_in[10];
    int Bn = in_sizes[0] / 128;

    cudaFuncSetAttribute(gen_main<2>, cudaFuncAttributeMaxDynamicSharedMemorySize, SMEM_TOTAL);
    cudaFuncSetAttribute(gen_main<1>, cudaFuncAttributeMaxDynamicSharedMemorySize, SMEM_TOTAL);

    prep_weights<<<130, 256>>>(Wi, M, W1, W2);
    transpose_z<<<dim3(Bn / 32, 4), dim3(32, 8)>>>(z, Bn);

    int tiles = Bn / 128;                       // 1024
    int nPair = ((tiles / 2) / 148) * 148;      // 444 (3 full waves)
    int nSingle = tiles - 2 * nPair;            // 136 (1 partial wave)
    if (nPair > 0)
        gen_main<2><<<nPair, 256, SMEM_TOTAL>>>(x, bi, Wf, bf, b1, b2, (float*)d_out, Bn, 0);
    if (nSingle > 0)
        gen_main<1><<<nSingle, 256, SMEM_TOTAL>>>(x, bi, Wf, bf, b1, b2, (float*)d_out, Bn, nPair * 256);
}